// round 2
// baseline (speedup 1.0000x reference)
#include <cuda_runtime.h>
#include <cstdint>
#include <cstddef>

// Problem constants
#define B_ 4
#define T_ 2048
#define C_ 2048
#define H_ 16
#define D_ 128
#define QKV_LD 6144   // 3*C

// Scratch (allocation-free rule: __device__ globals)
__device__ float g_qkv[(size_t)B_ * T_ * 3 * C_];   // [B*T, 3C]
__device__ float g_att[(size_t)B_ * T_ * C_];       // [B*T, C]

// ---------------------------------------------------------------------------
// SGEMM (NT): C[m,n] = sum_k A[m,k] * B[n,k] + bias[n]
// BM=BN=128, BK=16, 256 threads, 8x8 microtile.
// ---------------------------------------------------------------------------
__global__ __launch_bounds__(256) void sgemm_nt_bias(
    const float* __restrict__ A, const float* __restrict__ Bm,
    const float* __restrict__ bias, float* __restrict__ Cm,
    int M, int N, int K)
{
    __shared__ __align__(16) float As[16 * 132];
    __shared__ __align__(16) float Bs[16 * 132];

    const int tid = threadIdx.x;
    const int tx = tid & 15;
    const int ty = tid >> 4;
    const int m0 = blockIdx.y * 128;
    const int n0 = blockIdx.x * 128;

    float acc[8][8];
#pragma unroll
    for (int i = 0; i < 8; ++i)
#pragma unroll
        for (int j = 0; j < 8; ++j) acc[i][j] = 0.0f;

    for (int k0 = 0; k0 < K; k0 += 16) {
        // Load A tile 128x16 (transposed into As[k][m])
#pragma unroll
        for (int p = tid; p < 512; p += 256) {
            int r  = p >> 2;
            int kq = (p & 3) << 2;
            float4 v = *(const float4*)(A + (size_t)(m0 + r) * K + k0 + kq);
            As[(kq + 0) * 132 + r] = v.x;
            As[(kq + 1) * 132 + r] = v.y;
            As[(kq + 2) * 132 + r] = v.z;
            As[(kq + 3) * 132 + r] = v.w;
        }
        // Load B tile 128x16 (transposed into Bs[k][n])
#pragma unroll
        for (int p = tid; p < 512; p += 256) {
            int r  = p >> 2;
            int kq = (p & 3) << 2;
            float4 v = *(const float4*)(Bm + (size_t)(n0 + r) * K + k0 + kq);
            Bs[(kq + 0) * 132 + r] = v.x;
            Bs[(kq + 1) * 132 + r] = v.y;
            Bs[(kq + 2) * 132 + r] = v.z;
            Bs[(kq + 3) * 132 + r] = v.w;
        }
        __syncthreads();

#pragma unroll
        for (int k = 0; k < 16; ++k) {
            float4 a0 = *(const float4*)(As + k * 132 + 4 * ty);
            float4 a1 = *(const float4*)(As + k * 132 + 64 + 4 * ty);
            float4 b0 = *(const float4*)(Bs + k * 132 + 4 * tx);
            float4 b1 = *(const float4*)(Bs + k * 132 + 64 + 4 * tx);
            float a[8] = {a0.x, a0.y, a0.z, a0.w, a1.x, a1.y, a1.z, a1.w};
            float b[8] = {b0.x, b0.y, b0.z, b0.w, b1.x, b1.y, b1.z, b1.w};
#pragma unroll
            for (int i = 0; i < 8; ++i)
#pragma unroll
                for (int j = 0; j < 8; ++j)
                    acc[i][j] = fmaf(a[i], b[j], acc[i][j]);
        }
        __syncthreads();
    }

    // Epilogue: add bias, write (vectorized in n)
#pragma unroll
    for (int i = 0; i < 8; ++i) {
        int m = m0 + ((i < 4) ? (4 * ty + i) : (64 + 4 * ty + i - 4));
        float* crow = Cm + (size_t)m * N;
        {
            int n = n0 + 4 * tx;
            float4 bv = *(const float4*)(bias + n);
            float4 o;
            o.x = acc[i][0] + bv.x; o.y = acc[i][1] + bv.y;
            o.z = acc[i][2] + bv.z; o.w = acc[i][3] + bv.w;
            *(float4*)(crow + n) = o;
        }
        {
            int n = n0 + 64 + 4 * tx;
            float4 bv = *(const float4*)(bias + n);
            float4 o;
            o.x = acc[i][4] + bv.x; o.y = acc[i][5] + bv.y;
            o.z = acc[i][6] + bv.z; o.w = acc[i][7] + bv.w;
            *(float4*)(crow + n) = o;
        }
    }
}

// ---------------------------------------------------------------------------
// RoPE in-place on q and k slices of g_qkv.
// theta computed in double then rounded once to fp32 (matches the reference's
// correctly-rounded fp32 power); angle multiply + sincos in fp32 like the ref.
// ---------------------------------------------------------------------------
__global__ __launch_bounds__(256) void rope_kernel(float* __restrict__ qkv)
{
    int gid = blockIdx.x * blockDim.x + threadIdx.x;   // < B*T*H*64 = 8388608
    int i   = gid & 63;
    int h   = (gid >> 6) & 15;
    int row = gid >> 10;                               // b*T + t
    int t   = row & (T_ - 1);

    // theta = 10000^(-i/64), rounded to f32 once
    float theta = (float)exp2(-(double)i * (13.287712379549449 / 64.0));
    float ang = (float)t * theta;
    float sv, cv;
    sincosf(ang, &sv, &cv);

    size_t base = (size_t)row * QKV_LD + h * D_ + 2 * i;
    float q1 = qkv[base], q2 = qkv[base + 1];
    qkv[base]     = q1 * cv - q2 * sv;
    qkv[base + 1] = q1 * sv + q2 * cv;
    float k1 = qkv[base + C_], k2 = qkv[base + C_ + 1];
    qkv[base + C_]     = k1 * cv - k2 * sv;
    qkv[base + C_ + 1] = k1 * sv + k2 * cv;
}

// ---------------------------------------------------------------------------
// Flash attention (fp32, causal). Block = 256 threads (16x16), BQ=BKV=64, D=128.
// Qt/Kt stored d-major so the QK^T inner loop is two LDS.128 per 16 FMA.
// P stored transposed for the PV loop.
// smem: Qt[128][68] + Kt[128][68] + Vs[64][128] + Pt[64][68] = 119808 B.
// ---------------------------------------------------------------------------
#define FLASH_SMEM_FLOATS (128*68 + 128*68 + 64*128 + 64*68)

__global__ __launch_bounds__(256) void flash_attn(
    const float* __restrict__ qkv, float* __restrict__ outp)
{
    extern __shared__ __align__(16) float sm[];
    float* Qt = sm;                       // [128][68]  Qt[d][r]
    float* Kt = Qt + 128 * 68;            // [128][68]  Kt[d][c]
    float* Vs = Kt + 128 * 68;            // [64][128]  Vs[s][d]
    float* Pt = Vs + 64 * 128;            // [64][68]   Pt[s][r]

    const int tid = threadIdx.x;
    const int tx = tid & 15;
    const int ty = tid >> 4;
    const int bh = blockIdx.y;
    const int b = bh >> 4;
    const int h = bh & 15;
    const int qt = blockIdx.x;
    const int t0 = qt * 64;
    const float scale = 0.08838834764831845f;   // 1/sqrt(128)

    const float* qbase = qkv + (size_t)b * T_ * QKV_LD + h * D_;

    // Load Q tile transposed: Qt[d][r]
#pragma unroll
    for (int p = tid; p < 64 * 32; p += 256) {
        int r  = p >> 5;
        int dq = (p & 31) << 2;
        float4 v = *(const float4*)(qbase + (size_t)(t0 + r) * QKV_LD + dq);
        Qt[(dq + 0) * 68 + r] = v.x;
        Qt[(dq + 1) * 68 + r] = v.y;
        Qt[(dq + 2) * 68 + r] = v.z;
        Qt[(dq + 3) * 68 + r] = v.w;
    }

    float m_r[4], l_r[4], o[4][8];
#pragma unroll
    for (int i = 0; i < 4; ++i) {
        m_r[i] = -1e30f;
        l_r[i] = 0.0f;
#pragma unroll
        for (int j = 0; j < 8; ++j) o[i][j] = 0.0f;
    }

    for (int j = 0; j <= qt; ++j) {
        __syncthreads();   // protect Kt/Vs/Pt against previous iteration readers

        const float* kb = qbase + C_ + (size_t)j * 64 * QKV_LD;
        const float* vb = kb + C_;
#pragma unroll
        for (int p = tid; p < 64 * 32; p += 256) {
            int r  = p >> 5;
            int dq = (p & 31) << 2;
            float4 kv = *(const float4*)(kb + (size_t)r * QKV_LD + dq);
            Kt[(dq + 0) * 68 + r] = kv.x;
            Kt[(dq + 1) * 68 + r] = kv.y;
            Kt[(dq + 2) * 68 + r] = kv.z;
            Kt[(dq + 3) * 68 + r] = kv.w;
            float4 vv = *(const float4*)(vb + (size_t)r * QKV_LD + dq);
            *(float4*)(Vs + r * 128 + dq) = vv;
        }
        __syncthreads();

        // S = Q @ K^T  (4x4 per thread)
        float s[4][4];
#pragma unroll
        for (int i = 0; i < 4; ++i)
#pragma unroll
            for (int jj = 0; jj < 4; ++jj) s[i][jj] = 0.0f;

#pragma unroll 8
        for (int d = 0; d < 128; ++d) {
            float4 q4 = *(const float4*)(Qt + d * 68 + 4 * ty);
            float4 k4 = *(const float4*)(Kt + d * 68 + 4 * tx);
            float qa[4] = {q4.x, q4.y, q4.z, q4.w};
            float ka[4] = {k4.x, k4.y, k4.z, k4.w};
#pragma unroll
            for (int i = 0; i < 4; ++i)
#pragma unroll
                for (int jj = 0; jj < 4; ++jj)
                    s[i][jj] = fmaf(qa[i], ka[jj], s[i][jj]);
        }

        const bool diag = (j == qt);
        float mt[4];
#pragma unroll
        for (int i = 0; i < 4; ++i) {
#pragma unroll
            for (int jj = 0; jj < 4; ++jj) {
                float v = s[i][jj] * scale;
                if (diag && (4 * tx + jj) > (4 * ty + i)) v = -1e30f;
                s[i][jj] = v;
            }
            float mm = fmaxf(fmaxf(s[i][0], s[i][1]), fmaxf(s[i][2], s[i][3]));
            mm = fmaxf(mm, __shfl_xor_sync(0xffffffffu, mm, 1));
            mm = fmaxf(mm, __shfl_xor_sync(0xffffffffu, mm, 2));
            mm = fmaxf(mm, __shfl_xor_sync(0xffffffffu, mm, 4));
            mm = fmaxf(mm, __shfl_xor_sync(0xffffffffu, mm, 8));
            mt[i] = mm;
        }

#pragma unroll
        for (int i = 0; i < 4; ++i) {
            float mn = fmaxf(m_r[i], mt[i]);
            float alpha = __expf(m_r[i] - mn);
            m_r[i] = mn;
            float rs = 0.0f;
#pragma unroll
            for (int jj = 0; jj < 4; ++jj) {
                float p = __expf(s[i][jj] - mn);
                s[i][jj] = p;
                rs += p;
            }
            rs += __shfl_xor_sync(0xffffffffu, rs, 1);
            rs += __shfl_xor_sync(0xffffffffu, rs, 2);
            rs += __shfl_xor_sync(0xffffffffu, rs, 4);
            rs += __shfl_xor_sync(0xffffffffu, rs, 8);
            l_r[i] = l_r[i] * alpha + rs;
#pragma unroll
            for (int jc = 0; jc < 8; ++jc) o[i][jc] *= alpha;
        }

        // Store P transposed: Pt[s][r]
#pragma unroll
        for (int jj = 0; jj < 4; ++jj)
#pragma unroll
            for (int i = 0; i < 4; ++i)
                Pt[(4 * tx + jj) * 68 + 4 * ty + i] = s[i][jj];
        __syncthreads();

        // O += P @ V
#pragma unroll 4
        for (int ss = 0; ss < 64; ++ss) {
            float4 p4  = *(const float4*)(Pt + ss * 68 + 4 * ty);
            float4 va  = *(const float4*)(Vs + ss * 128 + 4 * tx);
            float4 vb4 = *(const float4*)(Vs + ss * 128 + 64 + 4 * tx);
            float pa[4] = {p4.x, p4.y, p4.z, p4.w};
            float vv[8] = {va.x, va.y, va.z, va.w, vb4.x, vb4.y, vb4.z, vb4.w};
#pragma unroll
            for (int i = 0; i < 4; ++i)
#pragma unroll
                for (int jc = 0; jc < 8; ++jc)
                    o[i][jc] = fmaf(pa[i], vv[jc], o[i][jc]);
        }
    }

    // Write O / l  into [B*T, C] with head-interleaved columns
#pragma unroll
    for (int i = 0; i < 4; ++i) {
        float inv = 1.0f / l_r[i];
        int row = t0 + 4 * ty + i;
        float* ob = outp + (size_t)(b * T_ + row) * C_ + h * D_;
        float4 r0 = {o[i][0] * inv, o[i][1] * inv, o[i][2] * inv, o[i][3] * inv};
        *(float4*)(ob + 4 * tx) = r0;
        float4 r1 = {o[i][4] * inv, o[i][5] * inv, o[i][6] * inv, o[i][7] * inv};
        *(float4*)(ob + 64 + 4 * tx) = r1;
    }
}

// ---------------------------------------------------------------------------
// Launch
// ---------------------------------------------------------------------------
extern "C" void kernel_launch(void* const* d_in, const int* in_sizes, int n_in,
                              void* d_out, int out_size)
{
    const float* x     = (const float*)d_in[0];   // [B,T,C]
    const float* w_qkv = (const float*)d_in[1];   // [3C, C]
    const float* b_qkv = (const float*)d_in[2];   // [3C]
    const float* w_out = (const float*)d_in[3];   // [C, C]
    const float* b_out = (const float*)d_in[4];   // [C]
    float* out = (float*)d_out;

    float* qkv = nullptr;
    float* att = nullptr;
    cudaGetSymbolAddress((void**)&qkv, g_qkv);
    cudaGetSymbolAddress((void**)&att, g_att);

    // 1) QKV projection: [8192, 2048] @ [6144, 2048]^T + b  -> [8192, 6144]
    sgemm_nt_bias<<<dim3(6144 / 128, 8192 / 128), 256>>>(
        x, w_qkv, b_qkv, qkv, B_ * T_, 3 * C_, C_);

    // 2) RoPE on q,k in place
    rope_kernel<<<(B_ * T_ * H_ * 64) / 256, 256>>>(qkv);

    // 3) Flash attention
    const int flash_smem = FLASH_SMEM_FLOATS * (int)sizeof(float);
    cudaFuncSetAttribute(flash_attn, cudaFuncAttributeMaxDynamicSharedMemorySize, flash_smem);
    flash_attn<<<dim3(T_ / 64, B_ * H_), 256, flash_smem>>>(qkv, att);

    // 4) Output projection: [8192, 2048] @ [2048, 2048]^T + b -> out
    sgemm_nt_bias<<<dim3(2048 / 128, 8192 / 128), 256>>>(
        att, w_out, b_out, out, B_ * T_, C_, C_);
}